// round 14
// baseline (speedup 1.0000x reference)
#include <cuda_runtime.h>
#include <cuda_bf16.h>
#include <cstdint>

#define NN 20000
#define EE 640000
#define RR 65
#define FIN 128
#define HH1 64
#define HH2 32
#define BB 8192
#define SEG1 20096               /* 157*128 padded segment rows */
#define NTILE 157
#define NB (RR * NTILE)          /* 10205 tile buckets */
#define KEYS (RR * NN)
#define RCP1 4224                /* 66*64: rel 65 = root1 */
#define RCP2 2176                /* 68*32: rel 65 = root2, 66-67 zero */

#define OUT_RETOS  (BB*RR)
#define OUT_RETOSA (OUT_RETOS + 2*NN)
#define OUT_X2O    (OUT_RETOSA + 2*NN)

// conversion job flat ranges (tf32 floats)
#define CV_X   (2 * SEG1 * FIN)
#define CV_W1  (RCP1 * FIN)
#define CV_W2  (RCP2 * HH1)
#define CV_TOT (CV_X + CV_W1 + CV_W2)

#define NB_EDGE 2500
#define NB_H1   15000
#define NB_CONV ((CV_TOT + 255) / 256)
#define NB_CLEAN ((KEYS + 255) / 256)

// tf32 tile geometry: KC=32 floats/row-chunk, 144B padded row (128B data + 16B)
#define KCC 32
#define STRIDE_B 144
#define TILE_B (128 * STRIDE_B)      /* 18432 B per tensor tile */
#define STAGE_B (2 * TILE_B)         /* 36864 B per stage (A + B) */

// ---------------- scratch ------------------------------------------------------
__device__ float g_h1O[NN * HH1];
__device__ float g_h1A[NN * HH1];
__device__ float g_h1Aa[NN * HH1];
__device__ float g_x2o[NN * HH2];
__device__ float g_x2oa[NN * HH2];
__device__ float g_x2oaa[NN * HH2];
__device__ int   g_cnt0[KEYS];     // zero-init at load; re-zeroed by cls_k tail blocks
__device__ int   g_cnt1[KEYS];
__device__ __align__(16) float g_colsum[HH2];
__device__ __align__(16) float g_v[HH2];

// tile-bucket CSR: key = r*NTILE + (src>>7); record = {src, dst, scale_bits, 0}
__device__ int  g_bh0[NB], g_bh1[NB];
__device__ int  g_boff0[NB + 1], g_boff1[NB + 1];
__device__ int  g_bcur0[NB], g_bcur1[NB];
__device__ int4 g_ed0[EE], g_ed1[EE];

// tf32-rounded operands (segment-strided, fp32 storage)
__device__ float g_l1[2 * SEG1 * FIN];
__device__ float g_l2[3 * SEG1 * HH1];
__device__ float g_w1[RCP1 * FIN];
__device__ float g_w2[RCP2 * HH1];

// ---------------- helpers ------------------------------------------------------
__device__ __forceinline__ uint32_t smem_u32(const void* p) {
    uint32_t a;
    asm("{ .reg .u64 t; cvta.to.shared.u64 t, %1; cvt.u32.u64 %0, t; }" : "=r"(a) : "l"(p));
    return a;
}
__device__ __forceinline__ void cp16(uint32_t dst, const void* src) {
    asm volatile("cp.async.cg.shared.global [%0], [%1], 16;"
                 :: "r"(dst), "l"(src) : "memory");
}
__device__ __forceinline__ float to_tf32(float v) {
    uint32_t o;
    asm("cvt.rna.tf32.f32 %0, %1;" : "=r"(o) : "f"(v));
    return __uint_as_float(o);
}
__device__ __forceinline__ void mma1688(float* d, const uint32_t* a, const uint32_t* b) {
    asm volatile("mma.sync.aligned.m16n8k8.row.col.f32.tf32.tf32.f32 "
        "{%0,%1,%2,%3}, {%4,%5,%6,%7}, {%8,%9}, {%0,%1,%2,%3};"
        : "+f"(d[0]), "+f"(d[1]), "+f"(d[2]), "+f"(d[3])
        : "r"(a[0]), "r"(a[1]), "r"(a[2]), "r"(a[3]), "r"(b[0]), "r"(b[1]));
}
#define LDSM4(R0,R1,R2,R3,addr) \
    asm volatile("ldmatrix.sync.aligned.m8n8.x4.shared.b16 {%0,%1,%2,%3}, [%4];" \
        : "=r"(R0), "=r"(R1), "=r"(R2), "=r"(R3) : "r"(addr))

struct ScatAll {
    const int*  off[3][2];
    const int4* ed[3][2];
    float*      out[3][2];
};

// ---------------- fused tf32 GEMM + scatter + root (2-stage, ldmatrix) ---------
template<int K, int H>
__global__ void __launch_bounds__(256, 2)
gemm_fused(const float* __restrict__ A_g, const float* __restrict__ B_g, ScatAll P)
{
    constexpr int NC = K / KCC;             // 4 (L1) / 2 (L2) chunks
    extern __shared__ __align__(16) char sm[];

    const int tid = threadIdx.x;
    const int wid = tid >> 5, lane = tid & 31;
    const int gid = lane >> 2, tig = lane & 3;
    const int wm = wid & 1, wn = wid >> 1;
    const int m0 = blockIdx.x * 128;
    const int n0 = blockIdx.y * 128;
    const uint32_t smu = smem_u32(sm);

    const int seg = m0 / SEG1;
    const int mloc = m0 - seg * SEG1;
    const int tile = mloc >> 7;
    const int r_base = n0 / H;

    float acc[4][4][4] = {};

    // ldmatrix byte offsets (tf32 fragments via b16 ldmatrix; verified mapping)
    uint32_t a_off[4], b_off[2];
    #pragma unroll
    for (int mt = 0; mt < 4; mt++)
        a_off[mt] = (uint32_t)((wm * 64 + mt * 16 + (lane & 15)) * STRIDE_B
                               + ((lane & 16) ? 16 : 0));
    #pragma unroll
    for (int p = 0; p < 2; p++)
        b_off[p] = (uint32_t)((wn * 32 + p * 16 + (lane & 7) + ((lane & 16) ? 8 : 0)) * STRIDE_B
                              + ((lane & 8) ? 16 : 0));

    auto load_chunk = [&](int c, int s) {
        const int koff = c * KCC;
        const uint32_t st = smu + s * STAGE_B;
        #pragma unroll
        for (int j = 0; j < 8; j++) {
            int i = tid + j * 256;            // 0..2047
            int t = i >> 10;                  // 0=A, 1=B
            int row = (i >> 3) & 127;
            int ch = i & 7;
            int rg = (t == 0 ? m0 : n0) + row;
            cp16(st + t * TILE_B + row * STRIDE_B + ch * 16,
                 (t == 0 ? A_g : B_g) + (size_t)rg * K + koff + ch * 4);
        }
        asm volatile("cp.async.commit_group;" ::: "memory");
    };

    auto compute = [&](int s) {
        const uint32_t base = smu + s * STAGE_B;
        #pragma unroll
        for (int ks = 0; ks < 4; ks++) {
            const uint32_t kb = ks * 32;
            uint32_t a[4][4], b[4][2];
            #pragma unroll
            for (int mt = 0; mt < 4; mt++)
                LDSM4(a[mt][0], a[mt][1], a[mt][2], a[mt][3], base + a_off[mt] + kb);
            #pragma unroll
            for (int p = 0; p < 2; p++)
                LDSM4(b[2*p][0], b[2*p][1], b[2*p+1][0], b[2*p+1][1],
                      base + TILE_B + b_off[p] + kb);
            #pragma unroll
            for (int mt = 0; mt < 4; mt++)
                #pragma unroll
                for (int nt = 0; nt < 4; nt++)
                    mma1688(acc[mt][nt], a[mt], b[nt]);
        }
    };

    // 2-stage mainloop
    load_chunk(0, 0);
    #pragma unroll
    for (int c = 0; c < NC; c++) {
        if (c + 1 < NC) {
            load_chunk(c + 1, (c + 1) & 1);
            asm volatile("cp.async.wait_group 1;" ::: "memory");
        } else {
            asm volatile("cp.async.wait_group 0;" ::: "memory");
        }
        __syncthreads();
        compute(c & 1);
        __syncthreads();
    }

    // prefetch bucket ranges (overlap L2 latency with Dsm staging)
    int e_lo[2][128 / H], e_hi[2][128 / H];
    #pragma unroll
    for (int pq = 0; pq < 2; pq++)
        if (P.out[seg][pq]) {
            #pragma unroll
            for (int ri = 0; ri < 128 / H; ri++) {
                int r = r_base + ri;
                if (r < RR) {
                    int b = r * NTILE + tile;
                    e_lo[pq][ri] = __ldg(&P.off[seg][pq][b]);
                    e_hi[pq][ri] = __ldg(&P.off[seg][pq][b + 1]);
                } else { e_lo[pq][ri] = 0; e_hi[pq][ri] = 0; }
            }
        }

    // stage tile to SMEM
    float* Dsm = reinterpret_cast<float*>(sm);
    #pragma unroll
    for (int mt = 0; mt < 4; mt++) {
        int r = wm * 64 + mt * 16 + gid;
        #pragma unroll
        for (int nt = 0; nt < 4; nt++) {
            int c = wn * 32 + nt * 8 + tig * 2;
            *reinterpret_cast<float2*>(Dsm + r * 132 + c) =
                make_float2(acc[mt][nt][0], acc[mt][nt][1]);
            *reinterpret_cast<float2*>(Dsm + (r + 8) * 132 + c) =
                make_float2(acc[mt][nt][2], acc[mt][nt][3]);
        }
    }
    __syncthreads();

    // scatter: CSR edges for real relations, dense add for phantom root
    constexpr int TPE = H / 4;
    constexpr int NSUB = 256 / TPE;
    const int sub = tid / TPE, q = tid % TPE;
    const int end_src = (mloc + 128 <= NN) ? 128 : (NN - mloc);

    #pragma unroll
    for (int pq = 0; pq < 2; pq++) {
        float* outp = P.out[seg][pq];
        if (!outp) continue;
        const int4* ed = P.ed[seg][pq];
        #pragma unroll
        for (int ri = 0; ri < 128 / H; ri++) {
            int r = r_base + ri;
            if (r < RR) {
                for (int e = e_lo[pq][ri] + sub; e < e_hi[pq][ri]; e += NSUB) {
                    int4 rec = __ldg(&ed[e]);
                    float scale = __int_as_float(rec.z);
                    const float* p = Dsm + (rec.x - mloc) * 132 + ri * H + q * 4;
                    float4 v = *reinterpret_cast<const float4*>(p);
                    float4 w = make_float4(v.x * scale, v.y * scale, v.z * scale, v.w * scale);
                    atomicAdd(reinterpret_cast<float4*>(outp + (size_t)rec.y * H + q * 4), w);
                }
            } else if (r == RR) {
                for (int row = sub; row < end_src; row += NSUB) {
                    const float* p = Dsm + row * 132 + ri * H + q * 4;
                    float4 v = *reinterpret_cast<const float4*>(p);
                    atomicAdd(reinterpret_cast<float4*>(outp + (size_t)(mloc + row) * H + q * 4), v);
                }
            }
        }
    }
}

// ---------------- prep: edge counting + h1 bias init ---------------------------
__global__ void prep_k(const int* __restrict__ ei, const int* __restrict__ et0,
                       const int* __restrict__ et1, const float* __restrict__ b1) {
    int b = blockIdx.x;
    if (b < NB_EDGE) {
        int e = b * 256 + threadIdx.x;
        if (e >= EE) return;
        int s = ei[e], d = ei[EE + e];
        int r0 = et0[e], r1 = et1[e];
        atomicAdd(&g_cnt0[r0 * NN + d], 1);
        atomicAdd(&g_cnt1[r1 * NN + d], 1);
        atomicAdd(&g_bh0[r0 * NTILE + (s >> 7)], 1);
        atomicAdd(&g_bh1[r1 * NTILE + (s >> 7)], 1);
    } else {
        int i = (b - NB_EDGE) * 256 + threadIdx.x;
        if (i >= 3 * NN * HH1) return;
        int seg = i / (NN * HH1);
        int j = i - seg * (NN * HH1);
        float v = b1[j & (HH1 - 1)];
        ((seg == 0) ? g_h1O : (seg == 1) ? g_h1A : g_h1Aa)[j] = v;
    }
}
__global__ void bscan_k() {
    __shared__ int smi[1024];
    __shared__ int run;
    const int* hist = blockIdx.x ? g_bh1 : g_bh0;
    int* off = blockIdx.x ? g_boff1 : g_boff0;
    int* cur = blockIdx.x ? g_bcur1 : g_bcur0;
    int t = threadIdx.x;
    if (t == 0) run = 0;
    __syncthreads();
    for (int base = 0; base < NB; base += 1024) {
        int i = base + t;
        int v = (i < NB) ? hist[i] : 0;
        smi[t] = v;
        __syncthreads();
        for (int o = 1; o < 1024; o <<= 1) {
            int x = (t >= o) ? smi[t - o] : 0;
            __syncthreads();
            smi[t] += x;
            __syncthreads();
        }
        int r = run;
        if (i < NB) { int excl = smi[t] - v + r; off[i] = excl; cur[i] = excl; }
        __syncthreads();
        if (t == 1023) run = r + smi[1023];
        __syncthreads();
    }
    if (t == 0) off[NB] = EE;
}

// ---------------- fill CSR + all tf32 conversions (merged) ----------------------
__global__ void fillconv_k(const int* __restrict__ ei, const int* __restrict__ et0,
                           const int* __restrict__ et1,
                           const float* __restrict__ x_o, const float* __restrict__ x_a,
                           const float* __restrict__ W1, const float* __restrict__ root1,
                           const float* __restrict__ W2, const float* __restrict__ root2)
{
    int b = blockIdx.x;
    if (b < NB_EDGE) {
        int e = b * 256 + threadIdx.x;
        if (e >= EE) return;
        int s = ei[e], d = ei[EE + e];
        {
            int r = et0[e];
            float sc = 1.f / (float)max(__ldg(&g_cnt0[r * NN + d]), 1);
            int p = atomicAdd(&g_bcur0[r * NTILE + (s >> 7)], 1);
            g_ed0[p] = make_int4(s, d, __float_as_int(sc), 0);
        }
        {
            int r = et1[e];
            float sc = 1.f / (float)max(__ldg(&g_cnt1[r * NN + d]), 1);
            int p = atomicAdd(&g_bcur1[r * NTILE + (s >> 7)], 1);
            g_ed1[p] = make_int4(s, d, __float_as_int(sc), 0);
        }
        return;
    }
    int i = (b - NB_EDGE) * 256 + threadIdx.x;
    if (i >= CV_TOT) return;
    float v;
    float* dst;
    int j;
    if (i < CV_X) {
        j = i;
        int seg = j / (SEG1 * FIN);
        int jj = j - seg * (SEG1 * FIN);
        int row = jj / FIN, col = jj - row * FIN;
        v = (row < NN) ? (seg ? x_a : x_o)[row * FIN + col] : 0.f;
        dst = g_l1;
    } else if (i < CV_X + CV_W1) {
        j = i - CV_X;
        int c = j / FIN, k = j - c * FIN;
        int r = c / HH1;
        v = (r < RR) ? W1[(size_t)r * (FIN * HH1) + (size_t)k * HH1 + (c % HH1)]
          : (r == RR) ? root1[(size_t)k * HH1 + (c % HH1)] : 0.f;
        dst = g_w1;
    } else {
        j = i - CV_X - CV_W1;
        int c = j / HH1, k = j - c * HH1;
        int r = c / HH2;
        v = (r < RR) ? W2[(size_t)r * (HH1 * HH2) + (size_t)k * HH2 + (c % HH2)]
          : (r == RR) ? root2[(size_t)k * HH2 + (c % HH2)] : 0.f;
        dst = g_w2;
    }
    dst[j] = to_tf32(v);
}

__global__ void relu_conv_k(const float* __restrict__ b2) {
    int i = blockIdx.x * blockDim.x + threadIdx.x;
    if (i < 3 * SEG1 * HH1) {
        int seg = i / (SEG1 * HH1);
        int j = i - seg * (SEG1 * HH1);
        int row = j / HH1, col = j - row * HH1;
        float v = 0.f;
        if (row < NN) {
            float* arr = (seg == 0) ? g_h1O : (seg == 1) ? g_h1A : g_h1Aa;
            v = fmaxf(arr[row * HH1 + col], 0.f);
            arr[row * HH1 + col] = v;
        }
        g_l2[i] = to_tf32(v);
    }
    if (i < 3 * NN * HH2) {
        int seg = i / (NN * HH2);
        int j = i - seg * (NN * HH2);
        ((seg == 0) ? g_x2o : (seg == 1) ? g_x2oa : g_x2oaa)[j] = b2[j & (HH2 - 1)];
    }
}

// ---------------- readout / outputs --------------------------------------------
__global__ void colsum_k() {
    __shared__ float smf[256];
    int col = threadIdx.x & 31, grp = threadIdx.x >> 5;
    float s = 0.f;
    for (int n = blockIdx.x * 8 + grp; n < NN; n += gridDim.x * 8)
        s += g_x2o[n * HH2 + col];
    smf[threadIdx.x] = s;
    __syncthreads();
    if (threadIdx.x < 32) {
        float t = 0.f;
        #pragma unroll
        for (int g2 = 0; g2 < 8; g2++) t += smf[g2 * 32 + threadIdx.x];
        atomicAdd(&g_colsum[threadIdx.x], t);
    }
}
__global__ void finalize_k(const float* __restrict__ discW) {
    __shared__ float c[HH2];
    int t = threadIdx.x;
    float m = g_colsum[t] / (float)NN;
    c[t] = 1.f / (1.f + expf(-m));
    __syncwarp();
    float v = 0.f;
    #pragma unroll
    for (int k = 0; k < HH2; k++) v += discW[t * HH2 + k] * c[k];
    g_v[t] = v;
}
__global__ void ret_k(const float* __restrict__ dbp, float* __restrict__ out) {
    int n = blockIdx.x * blockDim.x + threadIdx.x;
    if (n >= NN) return;
    float db = dbp[0];
    float d0 = 0.f, d1 = 0.f, d2 = 0.f;
    float* xo_out = out + OUT_X2O + (size_t)n * HH2;
    #pragma unroll
    for (int k = 0; k < HH2; k += 4) {
        float4 v4 = *reinterpret_cast<const float4*>(&g_v[k]);
        float4 a  = *reinterpret_cast<const float4*>(&g_x2o[n * HH2 + k]);
        float4 b  = *reinterpret_cast<const float4*>(&g_x2oa[n * HH2 + k]);
        float4 c  = *reinterpret_cast<const float4*>(&g_x2oaa[n * HH2 + k]);
        d0 += a.x*v4.x + a.y*v4.y + a.z*v4.z + a.w*v4.w;
        d1 += b.x*v4.x + b.y*v4.y + b.z*v4.z + b.w*v4.w;
        d2 += c.x*v4.x + c.y*v4.y + c.z*v4.z + c.w*v4.w;
        *reinterpret_cast<float4*>(&xo_out[k]) = a;
    }
    out[OUT_RETOS  + 2 * n]     = d0 + db;
    out[OUT_RETOS  + 2 * n + 1] = d1 + db;
    out[OUT_RETOSA + 2 * n]     = d0 + db;
    out[OUT_RETOSA + 2 * n + 1] = d2 + db;
}
// cls + counter cleanup merged (cleanup blocks re-zero for NEXT invocation)
__global__ void cls_k(const int* __restrict__ idx, const float* __restrict__ f1,
                      const float* __restrict__ clsW, const float* __restrict__ clsB,
                      const float* __restrict__ attt, float* __restrict__ out)
{
    int b = blockIdx.x;
    if (b >= BB) {
        int i = (b - BB) * 256 + threadIdx.x * 2;  // 128 thr x 2 ints
        if (i < KEYS) { g_cnt0[i] = 0; g_cnt1[i] = 0; }
        if (i + 1 < KEYS) { g_cnt0[i + 1] = 0; g_cnt1[i + 1] = 0; }
        if (i < NB) { g_bh0[i] = 0; g_bh1[i] = 0; }
        if (i + 1 < NB) { g_bh0[i + 1] = 0; g_bh1[i + 1] = 0; }
        if (i < HH2) { g_colsum[i] = 0.f; g_colsum[i + 1] = 0.f; }
        return;
    }
    __shared__ float z[448];
    int t = threadIdx.x;
    int i0 = idx[b], i1 = idx[BB + b];
    float a0 = attt[0], a1 = attt[1];
    for (int k = t; k < 448; k += 128) {
        float val;
        if      (k < 64)  val = a0 * g_h1O[(size_t)i0 * 64 + k];
        else if (k < 96)  val = a1 * g_x2o[(size_t)i0 * 32 + (k - 64)];
        else if (k < 224) val = f1[(size_t)i0 * 128 + (k - 96)];
        else if (k < 288) val = a0 * g_h1O[(size_t)i1 * 64 + (k - 224)];
        else if (k < 320) val = a1 * g_x2o[(size_t)i1 * 32 + (k - 288)];
        else              val = f1[(size_t)i1 * 128 + (k - 320)];
        z[k] = val;
    }
    __syncthreads();
    if (t < RR) {
        float acc = clsB[t];
        #pragma unroll 4
        for (int k = 0; k < 448; k++) acc += z[k] * clsW[k * RR + t];
        out[(size_t)b * RR + t] = acc;
    }
}

// ---------------- launcher ------------------------------------------------------
extern "C" void kernel_launch(void* const* d_in, const int* in_sizes, int n_in,
                              void* d_out, int out_size)
{
    (void)in_sizes; (void)n_in; (void)out_size;
    const float* x_o   = (const float*)d_in[0];
    const float* x_a   = (const float*)d_in[1];
    const float* f1    = (const float*)d_in[2];
    const float* W1    = (const float*)d_in[3];
    const float* root1 = (const float*)d_in[4];
    const float* b1    = (const float*)d_in[5];
    const float* W2    = (const float*)d_in[6];
    const float* root2 = (const float*)d_in[7];
    const float* b2    = (const float*)d_in[8];
    const float* attt  = (const float*)d_in[9];
    const float* discW = (const float*)d_in[10];
    const float* discb = (const float*)d_in[11];
    const float* clsW  = (const float*)d_in[12];
    const float* clsb  = (const float*)d_in[13];
    const int*   ei    = (const int*)d_in[14];
    const int*   et0   = (const int*)d_in[15];
    const int*   et1   = (const int*)d_in[16];
    const int*   idx   = (const int*)d_in[17];
    float* out = (float*)d_out;

    float *h1O, *h1A, *h1Aa, *x2o, *x2oa, *x2oaa;
    cudaGetSymbolAddress((void**)&h1O,   g_h1O);
    cudaGetSymbolAddress((void**)&h1A,   g_h1A);
    cudaGetSymbolAddress((void**)&h1Aa,  g_h1Aa);
    cudaGetSymbolAddress((void**)&x2o,   g_x2o);
    cudaGetSymbolAddress((void**)&x2oa,  g_x2oa);
    cudaGetSymbolAddress((void**)&x2oaa, g_x2oaa);

    int *boff0, *boff1;
    int4 *ed0, *ed1;
    cudaGetSymbolAddress((void**)&boff0, g_boff0); cudaGetSymbolAddress((void**)&boff1, g_boff1);
    cudaGetSymbolAddress((void**)&ed0, g_ed0);     cudaGetSymbolAddress((void**)&ed1, g_ed1);

    float *l1, *l2, *w1, *w2;
    cudaGetSymbolAddress((void**)&l1, g_l1); cudaGetSymbolAddress((void**)&l2, g_l2);
    cudaGetSymbolAddress((void**)&w1, g_w1); cudaGetSymbolAddress((void**)&w2, g_w2);

    const int SMP = 2 * STAGE_B;           // 73728 (>= 67584 Dsm)
    cudaFuncSetAttribute(gemm_fused<FIN, HH1>, cudaFuncAttributeMaxDynamicSharedMemorySize, SMP);
    cudaFuncSetAttribute(gemm_fused<HH1, HH2>, cudaFuncAttributeMaxDynamicSharedMemorySize, SMP);

    // #1: count + h1 bias init
    prep_k<<<NB_EDGE + NB_H1, 256>>>(ei, et0, et1, b1);
    // #2: bucket scan
    bscan_k<<<2, 1024>>>();
    // #3: CSR fill + all tf32 conversions
    fillconv_k<<<NB_EDGE + NB_CONV, 256>>>(ei, et0, et1, x_o, x_a, W1, root1, W2, root2);

    // #4: layer-1 fused (GEMM + root + scatter) — ncu capture target
    {
        ScatAll P = {};
        P.off[0][0] = boff0; P.ed[0][0] = ed0; P.out[0][0] = h1O;
        P.off[0][1] = boff1; P.ed[0][1] = ed1; P.out[0][1] = h1Aa;
        P.off[1][0] = boff0; P.ed[1][0] = ed0; P.out[1][0] = h1A;
        gemm_fused<FIN, HH1><<<dim3(2 * NTILE, RCP1 / 128), 256, SMP>>>(l1, w1, P);
    }

    // #5: relu + layer-2 operand conversion + x2 bias init
    relu_conv_k<<<(3 * SEG1 * HH1 + 255) / 256, 256>>>(b2);

    // #6: layer-2 fused
    {
        ScatAll P = {};
        P.off[0][0] = boff0; P.ed[0][0] = ed0; P.out[0][0] = x2o;
        P.off[1][0] = boff0; P.ed[1][0] = ed0; P.out[1][0] = x2oa;
        P.off[2][0] = boff1; P.ed[2][0] = ed1; P.out[2][0] = x2oaa;
        gemm_fused<HH1, HH2><<<dim3(3 * NTILE, RCP2 / 128), 256, SMP>>>(l2, w2, P);
    }

    // #7-10: readout / outputs (+ counter cleanup riding on cls_k)
    colsum_k<<<80, 256>>>();
    finalize_k<<<1, 32>>>(discW);
    ret_k<<<(NN + 127) / 128, 128>>>(discb, out);
    cls_k<<<BB + NB_CLEAN, 128>>>(idx, f1, clsW, clsb, attt, out);
}

// round 15
// speedup vs baseline: 1.5992x; 1.5992x over previous
#include <cuda_runtime.h>
#include <cuda_bf16.h>
#include <cstdint>

#define NN 20000
#define EE 640000
#define RR 65
#define FIN 128
#define HH1 64
#define HH2 32
#define BB 8192
#define SEG1 20096               /* 157*128 padded segment rows */
#define NTILE 157
#define NB (RR * NTILE)          /* 10205 tile buckets */
#define KEYS (RR * NN)
#define RCP1 4224                /* 66*64: rel 65 = root1 */
#define RCP2 2176                /* 68*32: rel 65 = root2, 66-67 zero */

#define OUT_RETOS  (BB*RR)
#define OUT_RETOSA (OUT_RETOS + 2*NN)
#define OUT_X2O    (OUT_RETOSA + 2*NN)

// conversion job flat ranges (tf32 floats)
#define CV_X   (2 * SEG1 * FIN)
#define CV_W1  (RCP1 * FIN)
#define CV_W2  (RCP2 * HH1)
#define CV_TOT (CV_X + CV_W1 + CV_W2)

#define NB_EDGE 2500
#define NB_H1   15000
#define NB_CONV ((CV_TOT + 255) / 256)
#define NB_CLEAN ((KEYS + 255) / 256)

// tf32 tile geometry: KC=32 floats/row-chunk, 144B padded row (128B data + 16B)
#define KCC 32
#define STRIDE_B 144
#define S32 36                       /* row stride in words */
#define TILE_B (128 * STRIDE_B)      /* 18432 B per tensor tile */
#define STAGE_B (2 * TILE_B)         /* 36864 B per stage (A + B) */

// ---------------- scratch ------------------------------------------------------
__device__ float g_h1O[NN * HH1];
__device__ float g_h1A[NN * HH1];
__device__ float g_h1Aa[NN * HH1];
__device__ float g_x2o[NN * HH2];
__device__ float g_x2oa[NN * HH2];
__device__ float g_x2oaa[NN * HH2];
__device__ int   g_cnt0[KEYS];     // zero-init at load; re-zeroed by cls_k tail blocks
__device__ int   g_cnt1[KEYS];
__device__ __align__(16) float g_colsum[HH2];
__device__ __align__(16) float g_v[HH2];

// tile-bucket CSR: key = r*NTILE + (src>>7); record = {src, dst, scale_bits, 0}
__device__ int  g_bh0[NB], g_bh1[NB];
__device__ int  g_boff0[NB + 1], g_boff1[NB + 1];
__device__ int  g_bcur0[NB], g_bcur1[NB];
__device__ int4 g_ed0[EE], g_ed1[EE];

// tf32-rounded operands (segment-strided, fp32 storage)
__device__ float g_l1[2 * SEG1 * FIN];
__device__ float g_l2[3 * SEG1 * HH1];
__device__ float g_w1[RCP1 * FIN];
__device__ float g_w2[RCP2 * HH1];

// ---------------- helpers ------------------------------------------------------
__device__ __forceinline__ uint32_t smem_u32(const void* p) {
    uint32_t a;
    asm("{ .reg .u64 t; cvta.to.shared.u64 t, %1; cvt.u32.u64 %0, t; }" : "=r"(a) : "l"(p));
    return a;
}
__device__ __forceinline__ void cp16(uint32_t dst, const void* src) {
    asm volatile("cp.async.cg.shared.global [%0], [%1], 16;"
                 :: "r"(dst), "l"(src) : "memory");
}
__device__ __forceinline__ float to_tf32(float v) {
    uint32_t o;
    asm("cvt.rna.tf32.f32 %0, %1;" : "=r"(o) : "f"(v));
    return __uint_as_float(o);
}
__device__ __forceinline__ void mma1688(float* d, const uint32_t* a, const uint32_t* b) {
    asm volatile("mma.sync.aligned.m16n8k8.row.col.f32.tf32.tf32.f32 "
        "{%0,%1,%2,%3}, {%4,%5,%6,%7}, {%8,%9}, {%0,%1,%2,%3};"
        : "+f"(d[0]), "+f"(d[1]), "+f"(d[2]), "+f"(d[3])
        : "r"(a[0]), "r"(a[1]), "r"(a[2]), "r"(a[3]), "r"(b[0]), "r"(b[1]));
}

struct ScatAll {
    const int*  off[3][2];
    const int4* ed[3][2];
    float*      out[3][2];
};

// ---------------- fused tf32 GEMM + scatter + root (2-stage, LDS fragments) ----
template<int K, int H>
__global__ void __launch_bounds__(256, 2)
gemm_fused(const float* __restrict__ A_g, const float* __restrict__ B_g, ScatAll P)
{
    constexpr int NC = K / KCC;             // 4 (L1) / 2 (L2) chunks
    extern __shared__ __align__(16) char sm[];

    const int tid = threadIdx.x;
    const int wid = tid >> 5, lane = tid & 31;
    const int gid = lane >> 2, tig = lane & 3;
    const int wm = wid & 1, wn = wid >> 1;
    const int m0 = blockIdx.x * 128;
    const int n0 = blockIdx.y * 128;
    const uint32_t smu = smem_u32(sm);

    const int seg = m0 / SEG1;
    const int mloc = m0 - seg * SEG1;
    const int tile = mloc >> 7;
    const int r_base = n0 / H;

    float acc[4][4][4] = {};

    // per-thread word bases within a tile
    const int arow_w = (wm * 64 + gid) * S32 + tig;
    const int brow_w = (wn * 32 + gid) * S32 + tig;

    auto load_chunk = [&](int c, int s) {
        const int koff = c * KCC;
        const uint32_t st = smu + s * STAGE_B;
        #pragma unroll
        for (int j = 0; j < 8; j++) {
            int i = tid + j * 256;            // 0..2047
            int t = i >> 10;                  // 0=A, 1=B
            int row = (i >> 3) & 127;
            int ch = i & 7;
            int rg = (t == 0 ? m0 : n0) + row;
            cp16(st + t * TILE_B + row * STRIDE_B + ch * 16,
                 (t == 0 ? A_g : B_g) + (size_t)rg * K + koff + ch * 4);
        }
        asm volatile("cp.async.commit_group;" ::: "memory");
    };

    auto compute = [&](int s) {
        const uint32_t* As = reinterpret_cast<const uint32_t*>(sm + s * STAGE_B);
        const uint32_t* Bs = As + TILE_B / 4;
        #pragma unroll
        for (int ks = 0; ks < 4; ks++) {
            const int kb = ks * 8;
            uint32_t a[4][4], b[4][2];
            #pragma unroll
            for (int mt = 0; mt < 4; mt++) {
                int base = arow_w + mt * 16 * S32 + kb;
                a[mt][0] = As[base];
                a[mt][1] = As[base + 8 * S32];
                a[mt][2] = As[base + 4];
                a[mt][3] = As[base + 8 * S32 + 4];
            }
            #pragma unroll
            for (int nt = 0; nt < 4; nt++) {
                int base = brow_w + nt * 8 * S32 + kb;
                b[nt][0] = Bs[base];
                b[nt][1] = Bs[base + 4];
            }
            #pragma unroll
            for (int mt = 0; mt < 4; mt++)
                #pragma unroll
                for (int nt = 0; nt < 4; nt++)
                    mma1688(acc[mt][nt], a[mt], b[nt]);
        }
    };

    // 2-stage mainloop
    load_chunk(0, 0);
    #pragma unroll
    for (int c = 0; c < NC; c++) {
        if (c + 1 < NC) {
            load_chunk(c + 1, (c + 1) & 1);
            asm volatile("cp.async.wait_group 1;" ::: "memory");
        } else {
            asm volatile("cp.async.wait_group 0;" ::: "memory");
        }
        __syncthreads();
        compute(c & 1);
        __syncthreads();
    }

    // prefetch bucket ranges (overlap L2 latency with Dsm staging)
    int e_lo[2][128 / H], e_hi[2][128 / H];
    #pragma unroll
    for (int pq = 0; pq < 2; pq++)
        if (P.out[seg][pq]) {
            #pragma unroll
            for (int ri = 0; ri < 128 / H; ri++) {
                int r = r_base + ri;
                if (r < RR) {
                    int b = r * NTILE + tile;
                    e_lo[pq][ri] = __ldg(&P.off[seg][pq][b]);
                    e_hi[pq][ri] = __ldg(&P.off[seg][pq][b + 1]);
                } else { e_lo[pq][ri] = 0; e_hi[pq][ri] = 0; }
            }
        }

    // stage tile to SMEM
    float* Dsm = reinterpret_cast<float*>(sm);
    #pragma unroll
    for (int mt = 0; mt < 4; mt++) {
        int r = wm * 64 + mt * 16 + gid;
        #pragma unroll
        for (int nt = 0; nt < 4; nt++) {
            int c = wn * 32 + nt * 8 + tig * 2;
            *reinterpret_cast<float2*>(Dsm + r * 132 + c) =
                make_float2(acc[mt][nt][0], acc[mt][nt][1]);
            *reinterpret_cast<float2*>(Dsm + (r + 8) * 132 + c) =
                make_float2(acc[mt][nt][2], acc[mt][nt][3]);
        }
    }
    __syncthreads();

    // scatter: CSR edges for real relations, dense add for phantom root
    constexpr int TPE = H / 4;
    constexpr int NSUB = 256 / TPE;
    const int sub = tid / TPE, q = tid % TPE;
    const int end_src = (mloc + 128 <= NN) ? 128 : (NN - mloc);

    #pragma unroll
    for (int pq = 0; pq < 2; pq++) {
        float* outp = P.out[seg][pq];
        if (!outp) continue;
        const int4* ed = P.ed[seg][pq];
        #pragma unroll
        for (int ri = 0; ri < 128 / H; ri++) {
            int r = r_base + ri;
            if (r < RR) {
                for (int e = e_lo[pq][ri] + sub; e < e_hi[pq][ri]; e += NSUB) {
                    int4 rec = __ldg(&ed[e]);
                    float scale = __int_as_float(rec.z);
                    const float* p = Dsm + (rec.x - mloc) * 132 + ri * H + q * 4;
                    float4 v = *reinterpret_cast<const float4*>(p);
                    float4 w = make_float4(v.x * scale, v.y * scale, v.z * scale, v.w * scale);
                    atomicAdd(reinterpret_cast<float4*>(outp + (size_t)rec.y * H + q * 4), w);
                }
            } else if (r == RR) {
                for (int row = sub; row < end_src; row += NSUB) {
                    const float* p = Dsm + row * 132 + ri * H + q * 4;
                    float4 v = *reinterpret_cast<const float4*>(p);
                    atomicAdd(reinterpret_cast<float4*>(outp + (size_t)(mloc + row) * H + q * 4), v);
                }
            }
        }
    }
}

// ---------------- prep: edge counting + h1 bias init ---------------------------
__global__ void prep_k(const int* __restrict__ ei, const int* __restrict__ et0,
                       const int* __restrict__ et1, const float* __restrict__ b1) {
    int b = blockIdx.x;
    if (b < NB_EDGE) {
        int e = b * 256 + threadIdx.x;
        if (e >= EE) return;
        int s = ei[e], d = ei[EE + e];
        int r0 = et0[e], r1 = et1[e];
        atomicAdd(&g_cnt0[r0 * NN + d], 1);
        atomicAdd(&g_cnt1[r1 * NN + d], 1);
        atomicAdd(&g_bh0[r0 * NTILE + (s >> 7)], 1);
        atomicAdd(&g_bh1[r1 * NTILE + (s >> 7)], 1);
    } else {
        int i = (b - NB_EDGE) * 256 + threadIdx.x;
        if (i >= 3 * NN * HH1) return;
        int seg = i / (NN * HH1);
        int j = i - seg * (NN * HH1);
        float v = b1[j & (HH1 - 1)];
        ((seg == 0) ? g_h1O : (seg == 1) ? g_h1A : g_h1Aa)[j] = v;
    }
}
__global__ void bscan_k() {
    __shared__ int smi[1024];
    __shared__ int run;
    const int* hist = blockIdx.x ? g_bh1 : g_bh0;
    int* off = blockIdx.x ? g_boff1 : g_boff0;
    int* cur = blockIdx.x ? g_bcur1 : g_bcur0;
    int t = threadIdx.x;
    if (t == 0) run = 0;
    __syncthreads();
    for (int base = 0; base < NB; base += 1024) {
        int i = base + t;
        int v = (i < NB) ? hist[i] : 0;
        smi[t] = v;
        __syncthreads();
        for (int o = 1; o < 1024; o <<= 1) {
            int x = (t >= o) ? smi[t - o] : 0;
            __syncthreads();
            smi[t] += x;
            __syncthreads();
        }
        int r = run;
        if (i < NB) { int excl = smi[t] - v + r; off[i] = excl; cur[i] = excl; }
        __syncthreads();
        if (t == 1023) run = r + smi[1023];
        __syncthreads();
    }
    if (t == 0) off[NB] = EE;
}

// ---------------- fill CSR + all tf32 conversions (merged) ----------------------
__global__ void fillconv_k(const int* __restrict__ ei, const int* __restrict__ et0,
                           const int* __restrict__ et1,
                           const float* __restrict__ x_o, const float* __restrict__ x_a,
                           const float* __restrict__ W1, const float* __restrict__ root1,
                           const float* __restrict__ W2, const float* __restrict__ root2)
{
    int b = blockIdx.x;
    if (b < NB_EDGE) {
        int e = b * 256 + threadIdx.x;
        if (e >= EE) return;
        int s = ei[e], d = ei[EE + e];
        {
            int r = et0[e];
            float sc = 1.f / (float)max(__ldg(&g_cnt0[r * NN + d]), 1);
            int p = atomicAdd(&g_bcur0[r * NTILE + (s >> 7)], 1);
            g_ed0[p] = make_int4(s, d, __float_as_int(sc), 0);
        }
        {
            int r = et1[e];
            float sc = 1.f / (float)max(__ldg(&g_cnt1[r * NN + d]), 1);
            int p = atomicAdd(&g_bcur1[r * NTILE + (s >> 7)], 1);
            g_ed1[p] = make_int4(s, d, __float_as_int(sc), 0);
        }
        return;
    }
    int i = (b - NB_EDGE) * 256 + threadIdx.x;
    if (i >= CV_TOT) return;
    float v;
    float* dst;
    int j;
    if (i < CV_X) {
        j = i;
        int seg = j / (SEG1 * FIN);
        int jj = j - seg * (SEG1 * FIN);
        int row = jj / FIN, col = jj - row * FIN;
        v = (row < NN) ? (seg ? x_a : x_o)[row * FIN + col] : 0.f;
        dst = g_l1;
    } else if (i < CV_X + CV_W1) {
        j = i - CV_X;
        int c = j / FIN, k = j - c * FIN;
        int r = c / HH1;
        v = (r < RR) ? W1[(size_t)r * (FIN * HH1) + (size_t)k * HH1 + (c % HH1)]
          : (r == RR) ? root1[(size_t)k * HH1 + (c % HH1)] : 0.f;
        dst = g_w1;
    } else {
        j = i - CV_X - CV_W1;
        int c = j / HH1, k = j - c * HH1;
        int r = c / HH2;
        v = (r < RR) ? W2[(size_t)r * (HH1 * HH2) + (size_t)k * HH2 + (c % HH2)]
          : (r == RR) ? root2[(size_t)k * HH2 + (c % HH2)] : 0.f;
        dst = g_w2;
    }
    dst[j] = to_tf32(v);
}

__global__ void relu_conv_k(const float* __restrict__ b2) {
    int i = blockIdx.x * blockDim.x + threadIdx.x;
    if (i < 3 * SEG1 * HH1) {
        int seg = i / (SEG1 * HH1);
        int j = i - seg * (SEG1 * HH1);
        int row = j / HH1, col = j - row * HH1;
        float v = 0.f;
        if (row < NN) {
            float* arr = (seg == 0) ? g_h1O : (seg == 1) ? g_h1A : g_h1Aa;
            v = fmaxf(arr[row * HH1 + col], 0.f);
            arr[row * HH1 + col] = v;
        }
        g_l2[i] = to_tf32(v);
    }
    if (i < 3 * NN * HH2) {
        int seg = i / (NN * HH2);
        int j = i - seg * (NN * HH2);
        ((seg == 0) ? g_x2o : (seg == 1) ? g_x2oa : g_x2oaa)[j] = b2[j & (HH2 - 1)];
    }
}

// ---------------- readout / outputs --------------------------------------------
__global__ void colsum_k() {
    __shared__ float smf[256];
    int col = threadIdx.x & 31, grp = threadIdx.x >> 5;
    float s = 0.f;
    for (int n = blockIdx.x * 8 + grp; n < NN; n += gridDim.x * 8)
        s += g_x2o[n * HH2 + col];
    smf[threadIdx.x] = s;
    __syncthreads();
    if (threadIdx.x < 32) {
        float t = 0.f;
        #pragma unroll
        for (int g2 = 0; g2 < 8; g2++) t += smf[g2 * 32 + threadIdx.x];
        atomicAdd(&g_colsum[threadIdx.x], t);
    }
}
__global__ void finalize_k(const float* __restrict__ discW) {
    __shared__ float c[HH2];
    int t = threadIdx.x;
    float m = g_colsum[t] / (float)NN;
    c[t] = 1.f / (1.f + expf(-m));
    __syncwarp();
    float v = 0.f;
    #pragma unroll
    for (int k = 0; k < HH2; k++) v += discW[t * HH2 + k] * c[k];
    g_v[t] = v;
}
__global__ void ret_k(const float* __restrict__ dbp, float* __restrict__ out) {
    int n = blockIdx.x * blockDim.x + threadIdx.x;
    if (n >= NN) return;
    float db = dbp[0];
    float d0 = 0.f, d1 = 0.f, d2 = 0.f;
    float* xo_out = out + OUT_X2O + (size_t)n * HH2;
    #pragma unroll
    for (int k = 0; k < HH2; k += 4) {
        float4 v4 = *reinterpret_cast<const float4*>(&g_v[k]);
        float4 a  = *reinterpret_cast<const float4*>(&g_x2o[n * HH2 + k]);
        float4 b  = *reinterpret_cast<const float4*>(&g_x2oa[n * HH2 + k]);
        float4 c  = *reinterpret_cast<const float4*>(&g_x2oaa[n * HH2 + k]);
        d0 += a.x*v4.x + a.y*v4.y + a.z*v4.z + a.w*v4.w;
        d1 += b.x*v4.x + b.y*v4.y + b.z*v4.z + b.w*v4.w;
        d2 += c.x*v4.x + c.y*v4.y + c.z*v4.z + c.w*v4.w;
        *reinterpret_cast<float4*>(&xo_out[k]) = a;
    }
    out[OUT_RETOS  + 2 * n]     = d0 + db;
    out[OUT_RETOS  + 2 * n + 1] = d1 + db;
    out[OUT_RETOSA + 2 * n]     = d0 + db;
    out[OUT_RETOSA + 2 * n + 1] = d2 + db;
}
// cls + counter cleanup merged (cleanup blocks re-zero for NEXT invocation)
__global__ void cls_k(const int* __restrict__ idx, const float* __restrict__ f1,
                      const float* __restrict__ clsW, const float* __restrict__ clsB,
                      const float* __restrict__ attt, float* __restrict__ out)
{
    int b = blockIdx.x;
    if (b >= BB) {
        int i = (b - BB) * 256 + threadIdx.x * 2;  // 128 thr x 2 ints
        if (i < KEYS) { g_cnt0[i] = 0; g_cnt1[i] = 0; }
        if (i + 1 < KEYS) { g_cnt0[i + 1] = 0; g_cnt1[i + 1] = 0; }
        if (i < NB) { g_bh0[i] = 0; g_bh1[i] = 0; }
        if (i + 1 < NB) { g_bh0[i + 1] = 0; g_bh1[i + 1] = 0; }
        if (i < HH2) { g_colsum[i] = 0.f; g_colsum[i + 1] = 0.f; }
        return;
    }
    __shared__ float z[448];
    int t = threadIdx.x;
    int i0 = idx[b], i1 = idx[BB + b];
    float a0 = attt[0], a1 = attt[1];
    for (int k = t; k < 448; k += 128) {
        float val;
        if      (k < 64)  val = a0 * g_h1O[(size_t)i0 * 64 + k];
        else if (k < 96)  val = a1 * g_x2o[(size_t)i0 * 32 + (k - 64)];
        else if (k < 224) val = f1[(size_t)i0 * 128 + (k - 96)];
        else if (k < 288) val = a0 * g_h1O[(size_t)i1 * 64 + (k - 224)];
        else if (k < 320) val = a1 * g_x2o[(size_t)i1 * 32 + (k - 288)];
        else              val = f1[(size_t)i1 * 128 + (k - 320)];
        z[k] = val;
    }
    __syncthreads();
    if (t < RR) {
        float acc = clsB[t];
        #pragma unroll 4
        for (int k = 0; k < 448; k++) acc += z[k] * clsW[k * RR + t];
        out[(size_t)b * RR + t] = acc;
    }
}

// ---------------- launcher ------------------------------------------------------
extern "C" void kernel_launch(void* const* d_in, const int* in_sizes, int n_in,
                              void* d_out, int out_size)
{
    (void)in_sizes; (void)n_in; (void)out_size;
    const float* x_o   = (const float*)d_in[0];
    const float* x_a   = (const float*)d_in[1];
    const float* f1    = (const float*)d_in[2];
    const float* W1    = (const float*)d_in[3];
    const float* root1 = (const float*)d_in[4];
    const float* b1    = (const float*)d_in[5];
    const float* W2    = (const float*)d_in[6];
    const float* root2 = (const float*)d_in[7];
    const float* b2    = (const float*)d_in[8];
    const float* attt  = (const float*)d_in[9];
    const float* discW = (const float*)d_in[10];
    const float* discb = (const float*)d_in[11];
    const float* clsW  = (const float*)d_in[12];
    const float* clsb  = (const float*)d_in[13];
    const int*   ei    = (const int*)d_in[14];
    const int*   et0   = (const int*)d_in[15];
    const int*   et1   = (const int*)d_in[16];
    const int*   idx   = (const int*)d_in[17];
    float* out = (float*)d_out;

    float *h1O, *h1A, *h1Aa, *x2o, *x2oa, *x2oaa;
    cudaGetSymbolAddress((void**)&h1O,   g_h1O);
    cudaGetSymbolAddress((void**)&h1A,   g_h1A);
    cudaGetSymbolAddress((void**)&h1Aa,  g_h1Aa);
    cudaGetSymbolAddress((void**)&x2o,   g_x2o);
    cudaGetSymbolAddress((void**)&x2oa,  g_x2oa);
    cudaGetSymbolAddress((void**)&x2oaa, g_x2oaa);

    int *boff0, *boff1;
    int4 *ed0, *ed1;
    cudaGetSymbolAddress((void**)&boff0, g_boff0); cudaGetSymbolAddress((void**)&boff1, g_boff1);
    cudaGetSymbolAddress((void**)&ed0, g_ed0);     cudaGetSymbolAddress((void**)&ed1, g_ed1);

    float *l1, *l2, *w1, *w2;
    cudaGetSymbolAddress((void**)&l1, g_l1); cudaGetSymbolAddress((void**)&l2, g_l2);
    cudaGetSymbolAddress((void**)&w1, g_w1); cudaGetSymbolAddress((void**)&w2, g_w2);

    const int SMP = 2 * STAGE_B;           // 73728 (>= 67584 Dsm)
    cudaFuncSetAttribute(gemm_fused<FIN, HH1>, cudaFuncAttributeMaxDynamicSharedMemorySize, SMP);
    cudaFuncSetAttribute(gemm_fused<HH1, HH2>, cudaFuncAttributeMaxDynamicSharedMemorySize, SMP);

    // #1: count + h1 bias init
    prep_k<<<NB_EDGE + NB_H1, 256>>>(ei, et0, et1, b1);
    // #2: bucket scan
    bscan_k<<<2, 1024>>>();
    // #3: CSR fill + all tf32 conversions
    fillconv_k<<<NB_EDGE + NB_CONV, 256>>>(ei, et0, et1, x_o, x_a, W1, root1, W2, root2);

    // #4: layer-1 fused (GEMM + root + scatter) — ncu capture target
    {
        ScatAll P = {};
        P.off[0][0] = boff0; P.ed[0][0] = ed0; P.out[0][0] = h1O;
        P.off[0][1] = boff1; P.ed[0][1] = ed1; P.out[0][1] = h1Aa;
        P.off[1][0] = boff0; P.ed[1][0] = ed0; P.out[1][0] = h1A;
        gemm_fused<FIN, HH1><<<dim3(2 * NTILE, RCP1 / 128), 256, SMP>>>(l1, w1, P);
    }

    // #5: relu + layer-2 operand conversion + x2 bias init
    relu_conv_k<<<(3 * SEG1 * HH1 + 255) / 256, 256>>>(b2);

    // #6: layer-2 fused
    {
        ScatAll P = {};
        P.off[0][0] = boff0; P.ed[0][0] = ed0; P.out[0][0] = x2o;
        P.off[1][0] = boff0; P.ed[1][0] = ed0; P.out[1][0] = x2oa;
        P.off[2][0] = boff1; P.ed[2][1] = ed1; P.ed[2][0] = ed1; P.out[2][0] = x2oaa;
        gemm_fused<HH1, HH2><<<dim3(3 * NTILE, RCP2 / 128), 256, SMP>>>(l2, w2, P);
    }

    // #7-10: readout / outputs (+ counter cleanup riding on cls_k)
    colsum_k<<<80, 256>>>();
    finalize_k<<<1, 32>>>(discW);
    ret_k<<<(NN + 127) / 128, 128>>>(discb, out);
    cls_k<<<BB + NB_CLEAN, 128>>>(idx, f1, clsW, clsb, attt, out);
}